// round 3
// baseline (speedup 1.0000x reference)
#include <cuda_runtime.h>
#include <cstdint>

// Fixed problem shape: B=1, N=768, C_IN=C_OUT=16, R=8
#define N_PTS  768
#define A_GRP  3                        // output rows per block
#define N_GRPS (N_PTS / A_GRP)          // 256 blocks, one group each
#define NWARPS 8
#define NTHR   256
#define ITERS  (N_PTS / (NWARPS * 4))   // 24 (4 b's per warp-iteration via p)

typedef unsigned long long ull;

// smem float offsets
#define OFF_FEAT  0                     // sFeatT: 6144 ull  = 12288 floats (49152B)
#define OFF_GEOM  12288                 // sGeom : 768 float4 = 3072 floats
#define OFF_W     15360                 // sW    : 2048 floats
#define OFF_RED   17408                 // sRed  : 1728 ull   = 3456 floats
#define OFF_GBUF  20864                 // sGbuf : 384 floats
#define SMEM_FLOATS 21248               // 84992 bytes -> 2 blocks/SM (170KB < 228KB)

// ---------------------------------------------------------------------------
// One block == one group of A_GRP=3 output rows.
//   Lane = p*8 + r (p: b-slot 0..3, r: RBF basis 0..7).
//   Feature tile stored TRANSPOSED as sFeatT[k][b] (k = ull chunk 0..7):
//   p-lanes hit banks {2b,2b+2,2b+4,2b+6} -> conflict-free, no padding.
//   Accumulation: packed fma.rn.f32x2. Epilogue reduces + contracts with W.
// ---------------------------------------------------------------------------
__global__ void __launch_bounds__(NTHR, 2) conv_fused(
    const float* __restrict__ feat,    // [768,16]
    const float* __restrict__ geom,    // [768,3]
    const float* __restrict__ W,       // [8,16,16]
    const float* __restrict__ mu,      // [8]
    const float* __restrict__ gamma,   // [8]
    float scale,
    float* __restrict__ out)           // [768,16]
{
    extern __shared__ float smem[];
    ull*    sFeatT = (ull*)smem;
    float4* sGeom  = (float4*)(smem + OFF_GEOM);
    float*  sW     = smem + OFF_W;
    ull*    sRed   = (ull*)(smem + OFF_RED);     // [ai][r][warp(pad 9)][8 ull]
    float*  sGbuf  = smem + OFF_GBUF;            // [ai][128]

    const int tid = threadIdx.x;

    // ---- fill shared ----
    const ull* featU = (const ull*)feat;         // 768*8 ull
    for (int i = tid; i < N_PTS * 8; i += NTHR) {
        int b = i >> 3, k = i & 7;
        sFeatT[k * N_PTS + b] = featU[i];        // coalesced LDG, minor STS conflict
    }
    for (int b = tid; b < N_PTS; b += NTHR)
        sGeom[b] = make_float4(geom[3 * b], geom[3 * b + 1], geom[3 * b + 2], 0.f);
    for (int i = tid; i < 2048; i += NTHR)
        sW[i] = W[i];
    __syncthreads();

    const int lane = tid & 31;
    const int warp = tid >> 5;
    const int r    = lane & 7;
    const int p    = lane >> 3;

    // RBF: pw = -(kr*d + mr)^2 = -gamma*log2(e)*(d-mu)^2
    const float kr = sqrtf(__ldg(gamma + r) * 1.44269504088896f);
    const float mr = -__ldg(mu + r) * kr;

    const int a0 = blockIdx.x * A_GRP;

    float gax[A_GRP], gay[A_GRP], gaz[A_GRP];
    #pragma unroll
    for (int ai = 0; ai < A_GRP; ai++) {
        float4 ga = sGeom[a0 + ai];
        gax[ai] = ga.x; gay[ai] = ga.y; gaz[ai] = ga.z;
    }

    ull acc[A_GRP][8];
    #pragma unroll
    for (int ai = 0; ai < A_GRP; ai++)
        #pragma unroll
        for (int k = 0; k < 8; k++) acc[ai][k] = 0ull;

    const int bbase = warp * 4 + p;

    #pragma unroll 4
    for (int it = 0; it < ITERS; it++) {
        const int b = bbase + it * 32;
        const float4 gb = sGeom[b];
        ull rv[8];
        #pragma unroll
        for (int k = 0; k < 8; k++) rv[k] = sFeatT[k * N_PTS + b];

        #pragma unroll
        for (int ai = 0; ai < A_GRP; ai++) {
            float dx = gb.x - gax[ai];
            float dy = gb.y - gay[ai];
            float dz = gb.z - gaz[ai];
            float d2 = fmaf(dx, dx, 1e-9f);
            d2 = fmaf(dy, dy, d2);
            d2 = fmaf(dz, dz, d2);
            float d;
            asm("sqrt.approx.f32 %0, %1;" : "=f"(d) : "f"(d2));
            float v  = fmaf(d, kr, mr);
            float pw = v * (-v);
            float e;
            asm("ex2.approx.f32 %0, %1;" : "=f"(e) : "f"(pw));
            ull e2;
            asm("mov.b64 %0, {%1, %1};" : "=l"(e2) : "f"(e));
            #pragma unroll
            for (int k = 0; k < 8; k++)
                asm("fma.rn.f32x2 %0, %1, %2, %0;"
                    : "+l"(acc[ai][k]) : "l"(rv[k]), "l"(e2));
        }
    }

    // ---- reduce over p (lane bits 3,4), packed ----
    #pragma unroll
    for (int ai = 0; ai < A_GRP; ai++)
        #pragma unroll
        for (int k = 0; k < 8; k++) {
            ull o = __shfl_xor_sync(0xffffffffu, acc[ai][k], 8);
            asm("add.rn.f32x2 %0, %0, %1;" : "+l"(acc[ai][k]) : "l"(o));
            o = __shfl_xor_sync(0xffffffffu, acc[ai][k], 16);
            asm("add.rn.f32x2 %0, %0, %1;" : "+l"(acc[ai][k]) : "l"(o));
        }

    // ---- per-warp partials to smem: sRed[ai][r][warp][8 ull] (warp-dim pad 9)
    if (p == 0) {
        #pragma unroll
        for (int ai = 0; ai < A_GRP; ai++) {
            ull* dst = sRed + ((ai * 8 + r) * 9 + warp) * 8;
            #pragma unroll
            for (int k = 0; k < 8; k++) dst[k] = acc[ai][k];
        }
    }
    __syncthreads();

    // ---- cross-warp reduce + W contraction: warp ai owns row a0+ai ----
    if (warp < A_GRP) {
        const int ai = warp;
        const int rr = lane >> 2;
        const int jp = (lane & 3) * 2;           // ull offset in 8-ull row
        ull s0 = 0ull, s1 = 0ull;
        #pragma unroll
        for (int w = 0; w < NWARPS; w++) {
            const ull* src = sRed + ((ai * 8 + rr) * 9 + w) * 8 + jp;
            asm("add.rn.f32x2 %0, %0, %1;" : "+l"(s0) : "l"(src[0]));
            asm("add.rn.f32x2 %0, %0, %1;" : "+l"(s1) : "l"(src[1]));
        }
        ull* gdst = (ull*)(sGbuf + ai * 128);
        gdst[lane * 2]     = s0;                 // ull idx 2*lane == rr*8 + jp
        gdst[lane * 2 + 1] = s1;
        __syncwarp();

        if (lane < 16) {
            const int i = lane;
            float accum = 0.f;
            const float4* wv = (const float4*)sW;
            const float4* gv = (const float4*)(sGbuf + ai * 128);
            #pragma unroll
            for (int r2 = 0; r2 < 8; r2++)
                #pragma unroll
                for (int c = 0; c < 4; c++) {
                    float4 w4 = wv[(r2 * 16 + i) * 4 + c];
                    float4 g4 = gv[r2 * 4 + c];
                    accum = fmaf(w4.x, g4.x, accum);
                    accum = fmaf(w4.y, g4.y, accum);
                    accum = fmaf(w4.z, g4.z, accum);
                    accum = fmaf(w4.w, g4.w, accum);
                }
            out[(a0 + ai) * 16 + i] = accum * scale;
        }
    }
}

// ---------------------------------------------------------------------------
// Launch: single kernel, 256 blocks (2 resident per SM), graph-capturable.
// ---------------------------------------------------------------------------
extern "C" void kernel_launch(void* const* d_in, const int* in_sizes, int n_in,
                              void* d_out, int out_size)
{
    const float* feat  = (const float*)d_in[0];   // [1,768,16]
    const float* geom  = (const float*)d_in[1];   // [1,768,3]
    const float* W     = (const float*)d_in[2];   // [8,16,16]
    const float* mu    = (const float*)d_in[3];   // [8]
    const float* gamma = (const float*)d_in[4];   // [8]
    float* out = (float*)d_out;

    const int n_norm = in_sizes[1] / 3;           // N, host-side
    const float scale = 1.0f / sqrtf((float)n_norm);

    const size_t smem_bytes = (size_t)SMEM_FLOATS * sizeof(float);  // 84992
    cudaFuncSetAttribute(conv_fused,
                         cudaFuncAttributeMaxDynamicSharedMemorySize,
                         (int)smem_bytes);

    conv_fused<<<N_GRPS, NTHR, smem_bytes>>>(feat, geom, W, mu, gamma, scale, out);
}